// round 1
// baseline (speedup 1.0000x reference)
#include <cuda_runtime.h>

#define D_ 6
#define N_ 32768
#define K_ 16
#define DIN_ 64
#define DOUT_ 64
#define ROWS_ ((N_ + 1) * DOUT_)

// Ping-pong state buffers. Row 0 of each is the "no child" zero row.
__device__ float g_h0[ROWS_];
__device__ float g_h1[ROWS_];
__device__ float g_c0[ROWS_];
__device__ float g_c1[ROWS_];
__device__ float g_Ga[ROWS_];   // G = h @ U_f for the h in buffer 0
__device__ float g_Gb[ROWS_];
// Precomputed Wx for all depths: [6*N][256], cols = [f | i | u | o]
__device__ float g_Wx[(size_t)D_ * N_ * 4 * DOUT_];

__device__ __forceinline__ float sigf(float x) {
    return 1.0f / (1.0f + __expf(-x));
}
__device__ __forceinline__ float tanhf_(float x) {
    return 1.0f - 2.0f / (1.0f + __expf(2.0f * x));
}

// Zero the depth-0 state + G, and the permanent zero rows of the other parity.
__global__ void init_kernel() {
    int i = blockIdx.x * blockDim.x + threadIdx.x;
    if (i < ROWS_) { g_h0[i] = 0.f; g_c0[i] = 0.f; g_Ga[i] = 0.f; }
    if (i < DOUT_) { g_h1[i] = 0.f; g_c1[i] = 0.f; g_Gb[i] = 0.f; }
}

// Wx[n][q] = E[labels[n]] @ W_w + W_b, for all 6*N nodes.
// 256 threads; thread t owns output column t with W_w[:,t] register-cached.
// Each block handles 64 nodes with their embeddings staged in smem.
__global__ __launch_bounds__(256) void wx_kernel(const int* __restrict__ labels,
                                                 const float* __restrict__ E,
                                                 const float* __restrict__ Ww,
                                                 const float* __restrict__ Wb) {
    __shared__ float xs[64 * DIN_];
    __shared__ int lab_s[64];
    int t = threadIdx.x;
    int base = blockIdx.x * 64;
    if (t < 64) lab_s[t] = labels[base + t];
    __syncthreads();
    for (int e = t; e < 64 * DIN_; e += 256) {
        int i = e >> 6, dd = e & 63;
        xs[e] = E[(size_t)lab_s[i] * DIN_ + dd];
    }
    float w[DIN_];
#pragma unroll
    for (int dd = 0; dd < DIN_; dd++) w[dd] = Ww[dd * 256 + t];
    float b = Wb[t];
    __syncthreads();
    for (int i = 0; i < 64; i++) {
        const float4* x4 = reinterpret_cast<const float4*>(xs + (i << 6));
        float acc = b;
#pragma unroll
        for (int dd = 0; dd < DIN_ / 4; dd++) {
            float4 v = x4[dd];
            acc = fmaf(v.x, w[4 * dd + 0], acc);
            acc = fmaf(v.y, w[4 * dd + 1], acc);
            acc = fmaf(v.z, w[4 * dd + 2], acc);
            acc = fmaf(v.w, w[4 * dd + 3], acc);
        }
        g_Wx[(size_t)(base + i) * 256 + t] = acc;
    }
}

// One depth step. 256 threads process 4 nodes per iteration, 64 nodes/block.
// Phases: (1) gather children h/G/c -> h_sum, branch_f
//         (2) iuo = h_sum @ U_iuo   (smem weights, packed-4-node hs)
//         (3) gates -> new_c/new_h  (+ write output on last depth)
//         (4) G_next = new_h @ U_f  (fused projection for next depth)
__global__ __launch_bounds__(256) void node_kernel(const int* __restrict__ child_idx,
                                                   const float* __restrict__ Uf,
                                                   const float* __restrict__ Uiuo,
                                                   float* __restrict__ out,
                                                   int depth) {
    const float *h_prev, *c_prev, *G_prev;
    float *h_next, *c_next, *G_next;
    if (depth & 1) {
        h_prev = g_h1; c_prev = g_c1; G_prev = g_Gb;
        h_next = g_h0; c_next = g_c0; G_next = g_Ga;
    } else {
        h_prev = g_h0; c_prev = g_c0; G_prev = g_Ga;
        h_next = g_h1; c_next = g_c1; G_next = g_Gb;
    }

    extern __shared__ float sm[];
    float* Uiuo_s = sm;                 // 64*192 = 12288 floats
    float* Uf_s   = sm + 12288;         // 64*64  = 4096
    float* hs_s   = sm + 16384;         // [64][4] packed across 4 nodes
    float* iuo_s  = sm + 16640;         // [192][4]
    int*   cidx_s = (int*)(sm + 17408); // [4][16]

    int tid = threadIdx.x;
    for (int e = tid; e < 64 * 192; e += 256) Uiuo_s[e] = Uiuo[e];
    for (int e = tid; e < 64 * 64; e += 256) Uf_s[e] = Uf[e];
    __syncthreads();

    int r = tid >> 6;       // node lane 0..3
    int j = tid & 63;       // hidden dim
    const size_t dN = (size_t)depth * N_;

    for (int it = 0; it < 16; it++) {
        int n = blockIdx.x * 64 + it * 4 + r;
        const size_t nb = dN + n;

        if (j < K_) cidx_s[r * K_ + j] = child_idx[nb * K_ + j];
        float wfx = g_Wx[nb * 256 + j];
        __syncthreads();

        // Phase 1: gather children
        float hs = 0.f, bf = 0.f;
#pragma unroll
        for (int k = 0; k < K_; k++) {
            int c = cidx_s[r * K_ + k];
            if (c != 0) {
                int off = c * DOUT_ + j;
                float hv = __ldg(h_prev + off);
                float gv = __ldg(G_prev + off);
                float cv = __ldg(c_prev + off);
                hs += hv;
                bf = fmaf(cv, sigf(wfx + gv), bf);
            }
        }
        hs_s[j * 4 + r] = hs;
        __syncthreads();

        // Phase 2: iuo = h_sum @ U_iuo  (threads 0..191, 4 nodes per thread)
        if (tid < 192) {
            int q = tid;
            float a0 = 0.f, a1 = 0.f, a2 = 0.f, a3 = 0.f;
            const float4* h4 = reinterpret_cast<const float4*>(hs_s);
#pragma unroll 8
            for (int d2 = 0; d2 < 64; d2++) {
                float u = Uiuo_s[d2 * 192 + q];
                float4 hh = h4[d2];
                a0 = fmaf(hh.x, u, a0);
                a1 = fmaf(hh.y, u, a1);
                a2 = fmaf(hh.z, u, a2);
                a3 = fmaf(hh.w, u, a3);
            }
            reinterpret_cast<float4*>(iuo_s)[q] = make_float4(a0, a1, a2, a3);
        }
        __syncthreads();

        // Phase 3: gates + state update
        float ig = sigf(iuo_s[j * 4 + r]          + g_Wx[nb * 256 + 64 + j]);
        float ug = tanhf_(iuo_s[(64 + j) * 4 + r] + g_Wx[nb * 256 + 128 + j]);
        float og = sigf(iuo_s[(128 + j) * 4 + r]  + g_Wx[nb * 256 + 192 + j]);
        float nc = fmaf(ig, ug, bf);
        float nh = og * tanhf_(nc);
        size_t row = (size_t)(n + 1) * DOUT_;
        c_next[row + j] = nc;
        h_next[row + j] = nh;
        if (out) out[(size_t)n * DOUT_ + j] = nh;
        hs_s[j * 4 + r] = nh;   // reuse as nh_s
        __syncthreads();

        // Phase 4: G_next = new_h @ U_f (one output col per thread)
        {
            float a = 0.f;
#pragma unroll 8
            for (int d2 = 0; d2 < 64; d2++)
                a = fmaf(hs_s[d2 * 4 + r], Uf_s[d2 * 64 + j], a);
            G_next[row + j] = a;
        }
        __syncthreads();
    }
}

static const int NODE_SMEM = (12288 + 4096 + 256 + 768 + 64) * 4;  // 69,888 B

extern "C" void kernel_launch(void* const* d_in, const int* in_sizes, int n_in,
                              void* d_out, int out_size) {
    const int*   labels    = (const int*)d_in[0];
    const int*   child_idx = (const int*)d_in[1];
    const float* E         = (const float*)d_in[2];
    const float* Ww        = (const float*)d_in[3];
    const float* Wb        = (const float*)d_in[4];
    const float* Uf        = (const float*)d_in[5];
    const float* Uiuo      = (const float*)d_in[6];
    float*       out       = (float*)d_out;

    cudaFuncSetAttribute(node_kernel, cudaFuncAttributeMaxDynamicSharedMemorySize,
                         NODE_SMEM);

    init_kernel<<<(ROWS_ + 255) / 256, 256>>>();
    wx_kernel<<<(D_ * N_) / 64, 256>>>(labels, E, Ww, Wb);
    for (int d = 0; d < D_; d++) {
        node_kernel<<<N_ / 64, 256, NODE_SMEM>>>(child_idx, Uf, Uiuo,
                                                 (d == D_ - 1) ? out : nullptr, d);
    }
}

// round 2
// speedup vs baseline: 2.2048x; 2.2048x over previous
#include <cuda_runtime.h>

#define D_ 6
#define N_ 32768
#define K_ 16
#define DIN_ 64
#define DOUT_ 64
#define ROWS_ ((N_ + 1) * DOUT_)

// Ping-pong state buffers. Row 0 of each is the "no child" zero row.
__device__ float g_h0[ROWS_];
__device__ float g_h1[ROWS_];
__device__ float g_c0[ROWS_];
__device__ float g_c1[ROWS_];
__device__ float g_Ga[ROWS_];   // G = h @ U_f for the h in buffer 0
__device__ float g_Gb[ROWS_];
// Precomputed Wx for all depths: [6*N][256], cols = [f | i | u | o]
__device__ float g_Wx[(size_t)D_ * N_ * 4 * DOUT_];

__device__ __forceinline__ float sigf(float x) {
    return 1.0f / (1.0f + __expf(-x));
}
__device__ __forceinline__ float tanhf_(float x) {
    return 1.0f - 2.0f / (1.0f + __expf(2.0f * x));
}

__global__ void init_kernel() {
    int i = blockIdx.x * blockDim.x + threadIdx.x;
    if (i < ROWS_) { g_h0[i] = 0.f; g_c0[i] = 0.f; g_Ga[i] = 0.f; }
    if (i < DOUT_) { g_h1[i] = 0.f; g_c1[i] = 0.f; g_Gb[i] = 0.f; }
}

// Wx[n][q] = E[labels[n]] @ W_w + W_b, for all 6*N nodes.
__global__ __launch_bounds__(256) void wx_kernel(const int* __restrict__ labels,
                                                 const float* __restrict__ E,
                                                 const float* __restrict__ Ww,
                                                 const float* __restrict__ Wb) {
    __shared__ float xs[64 * DIN_];
    __shared__ int lab_s[64];
    int t = threadIdx.x;
    int base = blockIdx.x * 64;
    if (t < 64) lab_s[t] = labels[base + t];
    __syncthreads();
    for (int e = t; e < 64 * DIN_; e += 256) {
        int i = e >> 6, dd = e & 63;
        xs[e] = E[(size_t)lab_s[i] * DIN_ + dd];
    }
    float w[DIN_];
#pragma unroll
    for (int dd = 0; dd < DIN_; dd++) w[dd] = Ww[dd * 256 + t];
    float b = Wb[t];
    __syncthreads();
    for (int i = 0; i < 64; i++) {
        const float4* x4 = reinterpret_cast<const float4*>(xs + (i << 6));
        float acc = b;
#pragma unroll
        for (int dd = 0; dd < DIN_ / 4; dd++) {
            float4 v = x4[dd];
            acc = fmaf(v.x, w[4 * dd + 0], acc);
            acc = fmaf(v.y, w[4 * dd + 1], acc);
            acc = fmaf(v.z, w[4 * dd + 2], acc);
            acc = fmaf(v.w, w[4 * dd + 3], acc);
        }
        g_Wx[(size_t)(base + i) * 256 + t] = acc;
    }
}

// Warp-synchronous depth step: each warp owns TWO nodes end-to-end.
// No block barriers inside the node loop; h_sum / new_h are exchanged
// across the warp with __shfl_sync. U_iuo/U_f staged once in smem.
__global__ __launch_bounds__(256) void node_kernel(const int* __restrict__ child_idx,
                                                   const float* __restrict__ Uf,
                                                   const float* __restrict__ Uiuo,
                                                   float* __restrict__ out,
                                                   int depth) {
    const float *h_prev, *c_prev, *G_prev;
    float *h_next, *c_next, *G_next;
    if (depth & 1) {
        h_prev = g_h1; c_prev = g_c1; G_prev = g_Gb;
        h_next = g_h0; c_next = g_c0; G_next = g_Ga;
    } else {
        h_prev = g_h0; c_prev = g_c0; G_prev = g_Ga;
        h_next = g_h1; c_next = g_c1; G_next = g_Gb;
    }

    extern __shared__ float sm[];
    float* U_s  = sm;           // [64][192]  d-major, conflict-free scalar reads
    float* Uf_s = sm + 12288;   // [64][64]

    int tid = threadIdx.x;
    for (int e = tid; e < 64 * 192; e += 256) U_s[e] = Uiuo[e];
    for (int e = tid; e < 64 * 64; e += 256) Uf_s[e] = Uf[e];
    __syncthreads();   // only barrier in the kernel

    const int lane = tid & 31;
    const int gwarp = (blockIdx.x * 256 + tid) >> 5;
    const int nwarps = gridDim.x * 8;
    const size_t dN = (size_t)depth * N_;
    const unsigned FULL = 0xffffffffu;

    for (int p = gwarp; p < N_ / 2; p += nwarps) {
        const int nA = 2 * p, nB = 2 * p + 1;
        const size_t nbA = dN + nA, nbB = dN + nB;

        // lanes 0..15 hold node A's child idx, 16..31 node B's
        int ci = child_idx[(dN + (lane < 16 ? nA : nB)) * K_ + (lane & 15)];

        float wfxA0 = g_Wx[nbA * 256 + lane], wfxA1 = g_Wx[nbA * 256 + 32 + lane];
        float wfxB0 = g_Wx[nbB * 256 + lane], wfxB1 = g_Wx[nbB * 256 + 32 + lane];

        float hsA0 = 0.f, hsA1 = 0.f, bfA0 = 0.f, bfA1 = 0.f;
        float hsB0 = 0.f, hsB1 = 0.f, bfB0 = 0.f, bfB1 = 0.f;
        float accA[6] = {0.f, 0.f, 0.f, 0.f, 0.f, 0.f};
        float accB[6] = {0.f, 0.f, 0.f, 0.f, 0.f, 0.f};

        if (depth != 0) {   // depth 0: h_prev/c_prev/G_prev are all zero
            // ---- gather children ----
#pragma unroll 4
            for (int k = 0; k < K_; k++) {
                int cA = __shfl_sync(FULL, ci, k);
                int cB = __shfl_sync(FULL, ci, k + 16);
                if (cA) {
                    int off = cA * DOUT_ + lane;
                    float hv0 = __ldg(h_prev + off), hv1 = __ldg(h_prev + off + 32);
                    float gv0 = __ldg(G_prev + off), gv1 = __ldg(G_prev + off + 32);
                    float cv0 = __ldg(c_prev + off), cv1 = __ldg(c_prev + off + 32);
                    hsA0 += hv0; hsA1 += hv1;
                    bfA0 = fmaf(cv0, sigf(wfxA0 + gv0), bfA0);
                    bfA1 = fmaf(cv1, sigf(wfxA1 + gv1), bfA1);
                }
                if (cB) {
                    int off = cB * DOUT_ + lane;
                    float hv0 = __ldg(h_prev + off), hv1 = __ldg(h_prev + off + 32);
                    float gv0 = __ldg(G_prev + off), gv1 = __ldg(G_prev + off + 32);
                    float cv0 = __ldg(c_prev + off), cv1 = __ldg(c_prev + off + 32);
                    hsB0 += hv0; hsB1 += hv1;
                    bfB0 = fmaf(cv0, sigf(wfxB0 + gv0), bfB0);
                    bfB1 = fmaf(cv1, sigf(wfxB1 + gv1), bfB1);
                }
            }
            // ---- iuo = h_sum @ U_iuo (warp-local, shfl broadcast) ----
#pragma unroll 8
            for (int d = 0; d < 64; d++) {
                float hA = __shfl_sync(FULL, (d < 32) ? hsA0 : hsA1, d & 31);
                float hB = __shfl_sync(FULL, (d < 32) ? hsB0 : hsB1, d & 31);
                const float* Ud = U_s + d * 192 + lane;
#pragma unroll
                for (int m = 0; m < 6; m++) {
                    float u = Ud[m * 32];
                    accA[m] = fmaf(hA, u, accA[m]);
                    accB[m] = fmaf(hB, u, accB[m]);
                }
            }
        }

        // ---- gates ----
        float iA0 = sigf(accA[0] + g_Wx[nbA * 256 + 64 + lane]);
        float iA1 = sigf(accA[1] + g_Wx[nbA * 256 + 96 + lane]);
        float uA0 = tanhf_(accA[2] + g_Wx[nbA * 256 + 128 + lane]);
        float uA1 = tanhf_(accA[3] + g_Wx[nbA * 256 + 160 + lane]);
        float oA0 = sigf(accA[4] + g_Wx[nbA * 256 + 192 + lane]);
        float oA1 = sigf(accA[5] + g_Wx[nbA * 256 + 224 + lane]);
        float iB0 = sigf(accB[0] + g_Wx[nbB * 256 + 64 + lane]);
        float iB1 = sigf(accB[1] + g_Wx[nbB * 256 + 96 + lane]);
        float uB0 = tanhf_(accB[2] + g_Wx[nbB * 256 + 128 + lane]);
        float uB1 = tanhf_(accB[3] + g_Wx[nbB * 256 + 160 + lane]);
        float oB0 = sigf(accB[4] + g_Wx[nbB * 256 + 192 + lane]);
        float oB1 = sigf(accB[5] + g_Wx[nbB * 256 + 224 + lane]);

        float ncA0 = fmaf(iA0, uA0, bfA0), ncA1 = fmaf(iA1, uA1, bfA1);
        float ncB0 = fmaf(iB0, uB0, bfB0), ncB1 = fmaf(iB1, uB1, bfB1);
        float nhA0 = oA0 * tanhf_(ncA0), nhA1 = oA1 * tanhf_(ncA1);
        float nhB0 = oB0 * tanhf_(ncB0), nhB1 = oB1 * tanhf_(ncB1);

        if (out) {   // final depth: write result only, no next-state needed
            out[(size_t)nA * DOUT_ + lane] = nhA0;
            out[(size_t)nA * DOUT_ + 32 + lane] = nhA1;
            out[(size_t)nB * DOUT_ + lane] = nhB0;
            out[(size_t)nB * DOUT_ + 32 + lane] = nhB1;
        } else {
            const size_t rA = (size_t)(nA + 1) * DOUT_, rB = (size_t)(nB + 1) * DOUT_;
            h_next[rA + lane] = nhA0; h_next[rA + 32 + lane] = nhA1;
            h_next[rB + lane] = nhB0; h_next[rB + 32 + lane] = nhB1;
            c_next[rA + lane] = ncA0; c_next[rA + 32 + lane] = ncA1;
            c_next[rB + lane] = ncB0; c_next[rB + 32 + lane] = ncB1;

            // ---- G_next = new_h @ U_f (fused projection for next depth) ----
            float gA0 = 0.f, gA1 = 0.f, gB0 = 0.f, gB1 = 0.f;
#pragma unroll 8
            for (int d = 0; d < 64; d++) {
                float hA = __shfl_sync(FULL, (d < 32) ? nhA0 : nhA1, d & 31);
                float hB = __shfl_sync(FULL, (d < 32) ? nhB0 : nhB1, d & 31);
                float u0 = Uf_s[d * 64 + lane];
                float u1 = Uf_s[d * 64 + 32 + lane];
                gA0 = fmaf(hA, u0, gA0); gA1 = fmaf(hA, u1, gA1);
                gB0 = fmaf(hB, u0, gB0); gB1 = fmaf(hB, u1, gB1);
            }
            G_next[rA + lane] = gA0; G_next[rA + 32 + lane] = gA1;
            G_next[rB + lane] = gB0; G_next[rB + 32 + lane] = gB1;
        }
    }
}

static const int NODE_SMEM = (12288 + 4096) * 4;  // 65,536 B -> 3 CTAs/SM

extern "C" void kernel_launch(void* const* d_in, const int* in_sizes, int n_in,
                              void* d_out, int out_size) {
    const int*   labels    = (const int*)d_in[0];
    const int*   child_idx = (const int*)d_in[1];
    const float* E         = (const float*)d_in[2];
    const float* Ww        = (const float*)d_in[3];
    const float* Wb        = (const float*)d_in[4];
    const float* Uf        = (const float*)d_in[5];
    const float* Uiuo      = (const float*)d_in[6];
    float*       out       = (float*)d_out;

    cudaFuncSetAttribute(node_kernel, cudaFuncAttributeMaxDynamicSharedMemorySize,
                         NODE_SMEM);

    init_kernel<<<(ROWS_ + 255) / 256, 256>>>();
    wx_kernel<<<(D_ * N_) / 64, 256>>>(labels, E, Ww, Wb);
    for (int d = 0; d < D_; d++) {
        node_kernel<<<444, 256, NODE_SMEM>>>(child_idx, Uf, Uiuo,
                                             (d == D_ - 1) ? out : nullptr, d);
    }
}

// round 3
// speedup vs baseline: 2.8787x; 1.3056x over previous
#include <cuda_runtime.h>

#define D_ 6
#define N_ 32768
#define K_ 16
#define DIN_ 64
#define DOUT_ 64

// Packed ping-pong state: {h, c, G, pad} per (node_row, dim).
// Row 0 is the "no child" row but is never read (c==0 children are skipped).
__device__ float4 g_s0[(N_ + 1) * DOUT_];
__device__ float4 g_s1[(N_ + 1) * DOUT_];
// Precomputed Wx for all depths: [6*N][256], cols = [f | i | u | o]
__device__ float g_Wx[(size_t)D_ * N_ * 4 * DOUT_];

__device__ __forceinline__ float tanha(float x) {
    float y;
    asm("tanh.approx.f32 %0, %1;" : "=f"(y) : "f"(x));
    return y;
}
__device__ __forceinline__ float sigt(float x) {
    return fmaf(tanha(0.5f * x), 0.5f, 0.5f);
}

// Wx[n][q] = E[labels[n]] @ W_w + W_b, for all 6*N nodes.
__global__ __launch_bounds__(256) void wx_kernel(const int* __restrict__ labels,
                                                 const float* __restrict__ E,
                                                 const float* __restrict__ Ww,
                                                 const float* __restrict__ Wb) {
    __shared__ float xs[64 * DIN_];
    __shared__ int lab_s[64];
    int t = threadIdx.x;
    int base = blockIdx.x * 64;
    if (t < 64) lab_s[t] = labels[base + t];
    __syncthreads();
    for (int e = t; e < 64 * DIN_; e += 256) {
        int i = e >> 6, dd = e & 63;
        xs[e] = E[(size_t)lab_s[i] * DIN_ + dd];
    }
    float w[DIN_];
#pragma unroll
    for (int dd = 0; dd < DIN_; dd++) w[dd] = Ww[dd * 256 + t];
    float b = Wb[t];
    __syncthreads();
    for (int i = 0; i < 64; i++) {
        const float4* x4 = reinterpret_cast<const float4*>(xs + (i << 6));
        float acc = b;
#pragma unroll
        for (int dd = 0; dd < DIN_ / 4; dd++) {
            float4 v = x4[dd];
            acc = fmaf(v.x, w[4 * dd + 0], acc);
            acc = fmaf(v.y, w[4 * dd + 1], acc);
            acc = fmaf(v.z, w[4 * dd + 2], acc);
            acc = fmaf(v.w, w[4 * dd + 3], acc);
        }
        g_Wx[(size_t)(base + i) * 256 + t] = acc;
    }
}

// Warp-synchronous depth step: each warp owns FOUR nodes end-to-end.
// State is packed float4 {h,c,G}; activations use HW tanh.approx.
__global__ __launch_bounds__(256, 3) void node_kernel(const int* __restrict__ child_idx,
                                                      const float* __restrict__ Uf,
                                                      const float* __restrict__ Uiuo,
                                                      float* __restrict__ out,
                                                      int depth) {
    const float4* sp = (depth & 1) ? g_s1 : g_s0;
    float4* sn = (depth & 1) ? g_s0 : g_s1;

    extern __shared__ float sm[];
    float* U_s  = sm;           // [64][192]  d-major
    float* Uf_s = sm + 12288;   // [64][64]

    int tid = threadIdx.x;
    for (int e = tid; e < 64 * 192; e += 256) U_s[e] = Uiuo[e];
    for (int e = tid; e < 64 * 64; e += 256) Uf_s[e] = Uf[e];
    __syncthreads();   // only block barrier

    const int lane = tid & 31;
    const int gwarp = (blockIdx.x * 256 + tid) >> 5;
    const int nwarps = gridDim.x * 8;
    const size_t dN = (size_t)depth * N_;
    const unsigned FULL = 0xffffffffu;

    for (int p = gwarp; p < N_ / 4; p += nwarps) {
        const int n0 = 4 * p;

        // 64 child indices (4 nodes x 16) spread across two regs per lane
        int ci0 = child_idx[(dN + n0) * K_ + lane];
        int ci1 = child_idx[(dN + n0) * K_ + 32 + lane];

        // f-gate Wx values, 2 dims per node
        float wf[8];
#pragma unroll
        for (int q = 0; q < 4; q++) {
            const float* wq = g_Wx + (dN + n0 + q) * 256;
            wf[2 * q]     = __ldg(wq + lane);
            wf[2 * q + 1] = __ldg(wq + 32 + lane);
        }

        float hs[8] = {0.f}, bf[8] = {0.f};
        float acc[24] = {0.f};

        if (depth != 0) {
            // ---- gather children (packed float4 rows) ----
#pragma unroll 4
            for (int k = 0; k < K_; k++) {
#pragma unroll
                for (int q = 0; q < 4; q++) {
                    int sl = q * 16 + k;
                    int c = (sl < 32) ? __shfl_sync(FULL, ci0, sl)
                                      : __shfl_sync(FULL, ci1, sl - 32);
                    if (c) {
                        float4 s0 = __ldg(sp + c * DOUT_ + lane);
                        float4 s1 = __ldg(sp + c * DOUT_ + 32 + lane);
                        hs[2 * q] += s0.x;
                        hs[2 * q + 1] += s1.x;
                        bf[2 * q]     = fmaf(s0.y, sigt(wf[2 * q] + s0.z), bf[2 * q]);
                        bf[2 * q + 1] = fmaf(s1.y, sigt(wf[2 * q + 1] + s1.z), bf[2 * q + 1]);
                    }
                }
            }

            // ---- iuo = h_sum @ U_iuo (shfl broadcast, 4 nodes share U reads) ----
#pragma unroll 4
            for (int d = 0; d < 32; d++) {
                float hA = __shfl_sync(FULL, hs[0], d);
                float hB = __shfl_sync(FULL, hs[2], d);
                float hC = __shfl_sync(FULL, hs[4], d);
                float hD = __shfl_sync(FULL, hs[6], d);
                const float* Ud = U_s + d * 192 + lane;
#pragma unroll
                for (int m = 0; m < 6; m++) {
                    float u = Ud[m * 32];
                    acc[m]      = fmaf(hA, u, acc[m]);
                    acc[6 + m]  = fmaf(hB, u, acc[6 + m]);
                    acc[12 + m] = fmaf(hC, u, acc[12 + m]);
                    acc[18 + m] = fmaf(hD, u, acc[18 + m]);
                }
            }
#pragma unroll 4
            for (int d = 32; d < 64; d++) {
                float hA = __shfl_sync(FULL, hs[1], d - 32);
                float hB = __shfl_sync(FULL, hs[3], d - 32);
                float hC = __shfl_sync(FULL, hs[5], d - 32);
                float hD = __shfl_sync(FULL, hs[7], d - 32);
                const float* Ud = U_s + d * 192 + lane;
#pragma unroll
                for (int m = 0; m < 6; m++) {
                    float u = Ud[m * 32];
                    acc[m]      = fmaf(hA, u, acc[m]);
                    acc[6 + m]  = fmaf(hB, u, acc[6 + m]);
                    acc[12 + m] = fmaf(hC, u, acc[12 + m]);
                    acc[18 + m] = fmaf(hD, u, acc[18 + m]);
                }
            }
        }

        // ---- gates ----
        float nc0[4], nc1[4], nh0[4], nh1[4];
#pragma unroll
        for (int q = 0; q < 4; q++) {
            const float* wq = g_Wx + (dN + n0 + q) * 256;
            float ig0 = sigt(acc[6 * q + 0] + __ldg(wq + 64 + lane));
            float ig1 = sigt(acc[6 * q + 1] + __ldg(wq + 96 + lane));
            float ug0 = tanha(acc[6 * q + 2] + __ldg(wq + 128 + lane));
            float ug1 = tanha(acc[6 * q + 3] + __ldg(wq + 160 + lane));
            float og0 = sigt(acc[6 * q + 4] + __ldg(wq + 192 + lane));
            float og1 = sigt(acc[6 * q + 5] + __ldg(wq + 224 + lane));
            nc0[q] = fmaf(ig0, ug0, bf[2 * q]);
            nc1[q] = fmaf(ig1, ug1, bf[2 * q + 1]);
            nh0[q] = og0 * tanha(nc0[q]);
            nh1[q] = og1 * tanha(nc1[q]);
        }

        if (out) {   // final depth: write result only
#pragma unroll
            for (int q = 0; q < 4; q++) {
                out[(size_t)(n0 + q) * DOUT_ + lane] = nh0[q];
                out[(size_t)(n0 + q) * DOUT_ + 32 + lane] = nh1[q];
            }
        } else {
            // ---- G_next = new_h @ U_f ----
            float g0[4] = {0.f}, g1[4] = {0.f};
#pragma unroll 4
            for (int d = 0; d < 32; d++) {
                float hA = __shfl_sync(FULL, nh0[0], d);
                float hB = __shfl_sync(FULL, nh0[1], d);
                float hC = __shfl_sync(FULL, nh0[2], d);
                float hD = __shfl_sync(FULL, nh0[3], d);
                float u0 = Uf_s[d * 64 + lane];
                float u1 = Uf_s[d * 64 + 32 + lane];
                g0[0] = fmaf(hA, u0, g0[0]); g1[0] = fmaf(hA, u1, g1[0]);
                g0[1] = fmaf(hB, u0, g0[1]); g1[1] = fmaf(hB, u1, g1[1]);
                g0[2] = fmaf(hC, u0, g0[2]); g1[2] = fmaf(hC, u1, g1[2]);
                g0[3] = fmaf(hD, u0, g0[3]); g1[3] = fmaf(hD, u1, g1[3]);
            }
#pragma unroll 4
            for (int d = 32; d < 64; d++) {
                float hA = __shfl_sync(FULL, nh1[0], d - 32);
                float hB = __shfl_sync(FULL, nh1[1], d - 32);
                float hC = __shfl_sync(FULL, nh1[2], d - 32);
                float hD = __shfl_sync(FULL, nh1[3], d - 32);
                float u0 = Uf_s[d * 64 + lane];
                float u1 = Uf_s[d * 64 + 32 + lane];
                g0[0] = fmaf(hA, u0, g0[0]); g1[0] = fmaf(hA, u1, g1[0]);
                g0[1] = fmaf(hB, u0, g0[1]); g1[1] = fmaf(hB, u1, g1[1]);
                g0[2] = fmaf(hC, u0, g0[2]); g1[2] = fmaf(hC, u1, g1[2]);
                g0[3] = fmaf(hD, u0, g0[3]); g1[3] = fmaf(hD, u1, g1[3]);
            }
#pragma unroll
            for (int q = 0; q < 4; q++) {
                size_t row = (size_t)(n0 + q + 1) * DOUT_;
                sn[row + lane]      = make_float4(nh0[q], nc0[q], g0[q], 0.f);
                sn[row + 32 + lane] = make_float4(nh1[q], nc1[q], g1[q], 0.f);
            }
        }
    }
}

static const int NODE_SMEM = (12288 + 4096) * 4;  // 65,536 B -> 3 CTAs/SM

extern "C" void kernel_launch(void* const* d_in, const int* in_sizes, int n_in,
                              void* d_out, int out_size) {
    const int*   labels    = (const int*)d_in[0];
    const int*   child_idx = (const int*)d_in[1];
    const float* E         = (const float*)d_in[2];
    const float* Ww        = (const float*)d_in[3];
    const float* Wb        = (const float*)d_in[4];
    const float* Uf        = (const float*)d_in[5];
    const float* Uiuo      = (const float*)d_in[6];
    float*       out       = (float*)d_out;

    cudaFuncSetAttribute(node_kernel, cudaFuncAttributeMaxDynamicSharedMemorySize,
                         NODE_SMEM);

    wx_kernel<<<(D_ * N_) / 64, 256>>>(labels, E, Ww, Wb);
    for (int d = 0; d < D_; d++) {
        node_kernel<<<444, 256, NODE_SMEM>>>(child_idx, Uf, Uiuo,
                                             (d == D_ - 1) ? out : nullptr, d);
    }
}

// round 4
// speedup vs baseline: 4.1360x; 1.4368x over previous
#include <cuda_runtime.h>

#define D_ 6
#define N_ 32768
#define K_ 16
#define DIN_ 64
#define DOUT_ 64

typedef unsigned long long u64;

// SoA ping-pong state, packed 2 dims per u64 (f32x2). Row 0 = zero row for
// masked children: .bss zero-initialized and NEVER written -> always zero.
__device__ u64 g_h2[2][(N_ + 1) * 32];
__device__ u64 g_c2[2][(N_ + 1) * 32];
__device__ u64 g_G2[2][(N_ + 1) * 32];   // G = 0.5 * (h @ U_f), pre-halved
// Precomputed Wx for all depths: [6*N][256], cols = [f | i | u | o]
__device__ float g_Wx[(size_t)D_ * N_ * 4 * DOUT_];

#define HALF2 0x3F0000003F000000ULL   // {0.5f, 0.5f}

__device__ __forceinline__ u64 pk2(float lo, float hi) {
    u64 r; asm("mov.b64 %0, {%1,%2};" : "=l"(r) : "f"(lo), "f"(hi)); return r;
}
__device__ __forceinline__ void upk2(u64 v, float& lo, float& hi) {
    asm("mov.b64 {%0,%1}, %2;" : "=f"(lo), "=f"(hi) : "l"(v));
}
__device__ __forceinline__ u64 fma2_(u64 a, u64 b, u64 c) {
    u64 d; asm("fma.rn.f32x2 %0, %1, %2, %3;" : "=l"(d) : "l"(a), "l"(b), "l"(c)); return d;
}
__device__ __forceinline__ u64 add2_(u64 a, u64 b) {
    u64 d; asm("add.rn.f32x2 %0, %1, %2;" : "=l"(d) : "l"(a), "l"(b)); return d;
}
__device__ __forceinline__ u64 mul2_(u64 a, u64 b) {
    u64 d; asm("mul.rn.f32x2 %0, %1, %2;" : "=l"(d) : "l"(a), "l"(b)); return d;
}
__device__ __forceinline__ float tanha(float x) {
    float y; asm("tanh.approx.f32 %0, %1;" : "=f"(y) : "f"(x)); return y;
}
// sigmoid(2*arg) given arg already pre-halved: 0.5*tanh(arg)+0.5, packed
__device__ __forceinline__ u64 sig2h(u64 argHalf) {
    float a, b; upk2(argHalf, a, b);
    return fma2_(pk2(tanha(a), tanha(b)), HALF2, HALF2);
}
__device__ __forceinline__ u64 tanh2(u64 v) {
    float a, b; upk2(v, a, b);
    return pk2(tanha(a), tanha(b));
}

// Wx[n][q] = E[labels[n]] @ W_w + W_b, f32x2 over d-pairs.
__global__ __launch_bounds__(256) void wx_kernel(const int* __restrict__ labels,
                                                 const float* __restrict__ E,
                                                 const float* __restrict__ Ww,
                                                 const float* __restrict__ Wb) {
    __shared__ u64 xs2[64 * 32];
    __shared__ int lab_s[64];
    int t = threadIdx.x;
    int base = blockIdx.x * 64;
    if (t < 64) lab_s[t] = labels[base + t];
    __syncthreads();
    for (int e = t; e < 64 * 32; e += 256) {
        int i = e >> 5, d2 = e & 31;
        float2 v = reinterpret_cast<const float2*>(E + (size_t)lab_s[i] * DIN_)[d2];
        xs2[e] = pk2(v.x, v.y);
    }
    u64 w2[32];
#pragma unroll
    for (int d2 = 0; d2 < 32; d2++)
        w2[d2] = pk2(Ww[(2 * d2) * 256 + t], Ww[(2 * d2 + 1) * 256 + t]);
    float b = Wb[t];
    __syncthreads();
    for (int i = 0; i < 64; i++) {
        const u64* x = xs2 + (i << 5);
        u64 a = 0;
#pragma unroll
        for (int d2 = 0; d2 < 32; d2++) a = fma2_(x[d2], w2[d2], a);
        float l, h; upk2(a, l, h);
        g_Wx[(size_t)(base + i) * 256 + t] = b + l + h;
    }
}

// Warp-synchronous depth step: 4 nodes/warp, all math packed f32x2,
// branch-free gather through the zero row.
__global__ __launch_bounds__(256) void node_kernel(const int* __restrict__ child_idx,
                                                   const float* __restrict__ Uf,
                                                   const float* __restrict__ Uiuo,
                                                   float* __restrict__ out,
                                                   int depth) {
    const int rb = depth & 1, wb = rb ^ 1;
    const u64* __restrict__ hp = g_h2[rb];
    const u64* __restrict__ cp = g_c2[rb];
    const u64* __restrict__ Gp = g_G2[rb];
    u64* __restrict__ hn = g_h2[wb];
    u64* __restrict__ cn = g_c2[wb];
    u64* __restrict__ Gn = g_G2[wb];

    extern __shared__ u64 smu[];
    u64* U2  = smu;          // [64][96]: d-major, lane's col-pairs at m*32+lane
    u64* Uf2 = smu + 6144;   // [64][32], pre-scaled by 0.5

    int tid = threadIdx.x;
    for (int e = tid; e < 64 * 96; e += 256) {
        int d = e / 96, p = e % 96;
        int col = (p >> 5) * 64 + 2 * (p & 31);
        U2[e] = pk2(Uiuo[d * 192 + col], Uiuo[d * 192 + col + 1]);
    }
    for (int e = tid; e < 64 * 32; e += 256) {
        int d = e >> 5, l = e & 31;
        Uf2[e] = pk2(0.5f * Uf[d * 64 + 2 * l], 0.5f * Uf[d * 64 + 2 * l + 1]);
    }
    __syncthreads();   // only block barrier

    const int lane = tid & 31;
    const int gwarp = (blockIdx.x * 256 + tid) >> 5;
    const int nwarps = gridDim.x * 8;
    const size_t dN = (size_t)depth * N_;
    const unsigned FULL = 0xffffffffu;

    for (int p = gwarp; p < N_ / 4; p += nwarps) {
        const int n0 = 4 * p;

        int ci0 = child_idx[(dN + n0) * K_ + lane];
        int ci1 = child_idx[(dN + n0) * K_ + 32 + lane];

        u64 wfh[4];
#pragma unroll
        for (int q = 0; q < 4; q++) {
            const u64* wq = reinterpret_cast<const u64*>(g_Wx + (dN + n0 + q) * 256);
            wfh[q] = mul2_(__ldg(wq + lane), HALF2);
        }

        u64 hs[4] = {0, 0, 0, 0}, bf[4] = {0, 0, 0, 0};
        u64 acc[12] = {0, 0, 0, 0, 0, 0, 0, 0, 0, 0, 0, 0};

        if (depth != 0) {
            // ---- gather children: branch-free, zero row absorbs idx==0 ----
#pragma unroll 4
            for (int k = 0; k < K_; k++) {
#pragma unroll
                for (int q = 0; q < 4; q++) {
                    int sl = q * 16 + k;
                    int c = (sl < 32) ? __shfl_sync(FULL, ci0, sl)
                                      : __shfl_sync(FULL, ci1, sl - 32);
                    int off = c * 32 + lane;
                    u64 h2 = __ldg(hp + off);
                    u64 c2 = __ldg(cp + off);
                    u64 G2 = __ldg(Gp + off);
                    hs[q] = add2_(hs[q], h2);
                    bf[q] = fma2_(c2, sig2h(add2_(wfh[q], G2)), bf[q]);
                }
            }

            // ---- iuo = h_sum @ U_iuo (packed col-pairs, shfl broadcast) ----
            float hsl[4], hsh[4];
#pragma unroll
            for (int q = 0; q < 4; q++) upk2(hs[q], hsl[q], hsh[q]);
#pragma unroll 4
            for (int sl = 0; sl < 32; sl++) {
                const u64* Ue = U2 + (2 * sl) * 96 + lane;
                const u64* Uo = Ue + 96;
                u64 ue0 = Ue[0], ue1 = Ue[32], ue2 = Ue[64];
                u64 uo0 = Uo[0], uo1 = Uo[32], uo2 = Uo[64];
#pragma unroll
                for (int q = 0; q < 4; q++) {
                    float he = __shfl_sync(FULL, hsl[q], sl);
                    float ho = __shfl_sync(FULL, hsh[q], sl);
                    u64 he2 = pk2(he, he), ho2 = pk2(ho, ho);
                    acc[3 * q]     = fma2_(he2, ue0, acc[3 * q]);
                    acc[3 * q + 1] = fma2_(he2, ue1, acc[3 * q + 1]);
                    acc[3 * q + 2] = fma2_(he2, ue2, acc[3 * q + 2]);
                    acc[3 * q]     = fma2_(ho2, uo0, acc[3 * q]);
                    acc[3 * q + 1] = fma2_(ho2, uo1, acc[3 * q + 1]);
                    acc[3 * q + 2] = fma2_(ho2, uo2, acc[3 * q + 2]);
                }
            }
        }

        // ---- gates (packed) ----
        u64 nc[4], nh[4];
        float nl[4], nhg[4];
#pragma unroll
        for (int q = 0; q < 4; q++) {
            const u64* wq = reinterpret_cast<const u64*>(g_Wx + (dN + n0 + q) * 256);
            u64 ig = sig2h(mul2_(add2_(acc[3 * q],     __ldg(wq + 32 + lane)), HALF2));
            u64 ug = tanh2(add2_(acc[3 * q + 1],       __ldg(wq + 64 + lane)));
            u64 og = sig2h(mul2_(add2_(acc[3 * q + 2], __ldg(wq + 96 + lane)), HALF2));
            nc[q] = fma2_(ig, ug, bf[q]);
            nh[q] = mul2_(og, tanh2(nc[q]));
            upk2(nh[q], nl[q], nhg[q]);
        }

        if (out) {   // final depth: write result only
            u64* o64 = reinterpret_cast<u64*>(out);
#pragma unroll
            for (int q = 0; q < 4; q++) o64[(size_t)(n0 + q) * 32 + lane] = nh[q];
        } else {
            // ---- G_next = 0.5 * (new_h @ U_f) ----
            u64 g[4] = {0, 0, 0, 0};
#pragma unroll 4
            for (int sl = 0; sl < 32; sl++) {
                u64 ufe = Uf2[(2 * sl) * 32 + lane];
                u64 ufo = Uf2[(2 * sl + 1) * 32 + lane];
#pragma unroll
                for (int q = 0; q < 4; q++) {
                    float he = __shfl_sync(FULL, nl[q], sl);
                    float ho = __shfl_sync(FULL, nhg[q], sl);
                    g[q] = fma2_(pk2(he, he), ufe, g[q]);
                    g[q] = fma2_(pk2(ho, ho), ufo, g[q]);
                }
            }
#pragma unroll
            for (int q = 0; q < 4; q++) {
                size_t row = (size_t)(n0 + q + 1) * 32 + lane;
                hn[row] = nh[q];
                cn[row] = nc[q];
                Gn[row] = g[q];
            }
        }
    }
}

static const int NODE_SMEM = (6144 + 2048) * 8;  // 65,536 B

extern "C" void kernel_launch(void* const* d_in, const int* in_sizes, int n_in,
                              void* d_out, int out_size) {
    const int*   labels    = (const int*)d_in[0];
    const int*   child_idx = (const int*)d_in[1];
    const float* E         = (const float*)d_in[2];
    const float* Ww        = (const float*)d_in[3];
    const float* Wb        = (const float*)d_in[4];
    const float* Uf        = (const float*)d_in[5];
    const float* Uiuo      = (const float*)d_in[6];
    float*       out       = (float*)d_out;

    cudaFuncSetAttribute(node_kernel, cudaFuncAttributeMaxDynamicSharedMemorySize,
                         NODE_SMEM);

    wx_kernel<<<(D_ * N_) / 64, 256>>>(labels, E, Ww, Wb);
    for (int d = 0; d < D_; d++) {
        node_kernel<<<444, 256, NODE_SMEM>>>(child_idx, Uf, Uiuo,
                                             (d == D_ - 1) ? out : nullptr, d);
    }
}